// round 15
// baseline (speedup 1.0000x reference)
#include <cuda_runtime.h>
#include <cuda_fp16.h>
#include <math.h>
#include <stdint.h>

#define S_   2048
#define HID_ 2048
#define NH_  16
#define NKV_ 4
#define GRP_ (NH_/NKV_)   // 4
#define HD_  128
#define KVD_ (NKV_*HD_)   // 512

#define SCL_LOG2E 0.12751744f

// ---------------------------------------------------------------------------
// scratch (allocation-free: __device__ globals)
// ---------------------------------------------------------------------------
__device__ float g_q [S_*HID_],  g_q2[S_*HID_];
__device__ float g_k [S_*KVD_],  g_k2[S_*KVD_];
__device__ float g_v [S_*KVD_],  g_v2[S_*KVD_];

__device__ __half g_hs[S_*HID_];          // hidden, single fp16
__device__ __half g_wq[HID_*HID_];
__device__ __half g_wk[KVD_*HID_];
__device__ __half g_wv[KVD_*HID_];
__device__ __half g_wo[HID_*HID_];
__device__ __half g_at[S_*HID_];          // attn out, single fp16

__device__ __half g_qb_hi[S_*HID_],  g_qb_lo[S_*HID_];
__device__ __half g_kb[NKV_*S_*HD_];
__device__ __half g_vb[NKV_*S_*HD_];

// ---------------------------------------------------------------------------
// PTX helpers (plain sm_103-safe)
// ---------------------------------------------------------------------------
__device__ __forceinline__ uint32_t smem_to_u32(const void* p) {
    uint32_t a;
    asm("{ .reg .u64 t; cvta.to.shared.u64 t, %1; cvt.u32.u64 %0, t; }"
        : "=r"(a) : "l"(p));
    return a;
}
__device__ __forceinline__ void cp16(uint32_t dst, const void* src) {
    asm volatile("cp.async.cg.shared.global [%0], [%1], 16;" :: "r"(dst), "l"(src));
}
#define CP_COMMIT() asm volatile("cp.async.commit_group;" ::: "memory")
#define CP_WAIT(n)  asm volatile("cp.async.wait_group %0;" :: "n"(n) : "memory")

__device__ __forceinline__ void ldm_x4(uint32_t* r, uint32_t addr) {
    asm volatile("ldmatrix.sync.aligned.m8n8.x4.shared.b16 {%0,%1,%2,%3}, [%4];"
        : "=r"(r[0]), "=r"(r[1]), "=r"(r[2]), "=r"(r[3]) : "r"(addr));
}
__device__ __forceinline__ void ldm_x2(uint32_t* r, uint32_t addr) {
    asm volatile("ldmatrix.sync.aligned.m8n8.x2.shared.b16 {%0,%1}, [%2];"
        : "=r"(r[0]), "=r"(r[1]) : "r"(addr));
}
__device__ __forceinline__ void ldm_x4t(uint32_t* r, uint32_t addr) {
    asm volatile("ldmatrix.sync.aligned.m8n8.x4.trans.shared.b16 {%0,%1,%2,%3}, [%4];"
        : "=r"(r[0]), "=r"(r[1]), "=r"(r[2]), "=r"(r[3]) : "r"(addr));
}
__device__ __forceinline__ void mma_f16(float* c, const uint32_t* a, const uint32_t* b) {
    asm volatile("mma.sync.aligned.m16n8k16.row.col.f32.f16.f16.f32 "
        "{%0,%1,%2,%3}, {%4,%5,%6,%7}, {%8,%9}, {%0,%1,%2,%3};"
        : "+f"(c[0]), "+f"(c[1]), "+f"(c[2]), "+f"(c[3])
        : "r"(a[0]), "r"(a[1]), "r"(a[2]), "r"(a[3]), "r"(b[0]), "r"(b[1]));
}

__device__ __forceinline__ uint32_t pack_hi(float x, float y) {
    union { __half2 h2; uint32_t u; } H;
    H.h2 = __halves2half2(__float2half_rn(x), __float2half_rn(y));
    return H.u;
}

__device__ __forceinline__ float fexp2(float x) {
    x = fmaxf(x, -126.0f);
    int e = __float2int_rn(x);
    float f = x - (float)e;
    float p = 0.0018775767f;
    p = fmaf(p, f, 0.0089893397f);
    p = fmaf(p, f, 0.0558040221f);
    p = fmaf(p, f, 0.2402264923f);
    p = fmaf(p, f, 0.6931471825f);
    p = fmaf(p, f, 1.0f);
    return __int_as_float(__float_as_int(p) + (e << 23));
}

__device__ __forceinline__ void split_f16(float v, __half* hi, __half* lo) {
    __half h = __float2half_rn(v);
    *hi = h;
    *lo = __float2half_rn(v - __half2float(h));
}

__device__ __forceinline__ void rope_pair(float x1, float x2, int pos, int d,
                                          float& o1, float& o2)
{
    float inv = exp2f((float)d * (-13.287712379549449f / 64.0f));
    float ang = (float)pos * inv;
    float sn, cs;
    sincosf(ang, &sn, &cs);
    o1 = x1 * cs - x2 * sn;
    o2 = x1 * sn + x2 * cs;
}

// ---------------------------------------------------------------------------
__global__ void conv_half_kernel(const float* __restrict__ src,
                                 __half* __restrict__ dst)
{
    int i = blockIdx.x * 256 + threadIdx.x;
    float4 v = ((const float4*)src)[i];
    union { uint2 u; __half b[4]; } H;
    H.b[0] = __float2half_rn(v.x); H.b[1] = __float2half_rn(v.y);
    H.b[2] = __float2half_rn(v.z); H.b[3] = __float2half_rn(v.w);
    ((uint2*)dst)[i] = H.u;
}

__global__ void transpose_half2_kernel(const float* __restrict__ W0,
                                       __half* __restrict__ O0,
                                       const float* __restrict__ W1,
                                       __half* __restrict__ O1,
                                       int Kd, int Nd)
{
    __shared__ float t[32][33];
    const float* W = blockIdx.z ? W1 : W0;
    __half* out    = blockIdx.z ? O1 : O0;
    int bn = blockIdx.x * 32;
    int bk = blockIdx.y * 32;
    int x = threadIdx.x, y = threadIdx.y;
    #pragma unroll
    for (int i = 0; i < 32; i += 8)
        t[y + i][x] = W[(size_t)(bk + y + i) * Nd + bn + x];
    __syncthreads();
    #pragma unroll
    for (int i = 0; i < 32; i += 8)
        out[(size_t)(bn + y + i) * Kd + bk + x] = __float2half_rn(t[x][y + i]);
}

// ---------------------------------------------------------------------------
// 1-product fp16 GEMM body: C = A @ Bh^T.  128x128 tile, K-chunks of 32,
// 3-stage cp.async, 2 CTAs/SM.  Klen may differ from lda (split-K).
// ---------------------------------------------------------------------------
#define TILE_B   10240
#define BUF1_B   (2*TILE_B)
#define GEMM1_SMEM (3*BUF1_B)   // 61440

__device__ __forceinline__ void load_tile_async(uint32_t sdst,
                                                const __half* g,
                                                int ldk, int tid)
{
    int r   = tid >> 2;
    int seg = tid & 3;
    #pragma unroll
    for (int h = 0; h < 2; ++h) {
        int row = r + h * 64;
        cp16(sdst + row * 80 + seg * 16, g + (size_t)row * ldk + seg * 8);
    }
}

__device__ __forceinline__ void gemm1_body(
    uint32_t sb,
    const __half* A, const __half* Bh,
    float* C, int N, int Klen, int lda, int tid)
{
    const int lane = tid & 31, wid = tid >> 5;
    const int wm = wid & 1, wn = wid >> 1;

    float acc[4][4][4];
    #pragma unroll
    for (int mi = 0; mi < 4; ++mi)
        #pragma unroll
        for (int ni = 0; ni < 4; ++ni)
            #pragma unroll
            for (int q = 0; q < 4; ++q) acc[mi][ni][q] = 0.f;

    const int T = Klen / 32;
    load_tile_async(sb,                   A,       lda, tid);
    load_tile_async(sb + TILE_B,          Bh,      lda, tid);
    CP_COMMIT();
    load_tile_async(sb + BUF1_B,          A + 32,  lda, tid);
    load_tile_async(sb + BUF1_B + TILE_B, Bh + 32, lda, tid);
    CP_COMMIT();

    const uint32_t a_lane_off = (uint32_t)((lane & 15) * 80 + (lane >> 4) * 16);
    const uint32_t b_lane_off = (uint32_t)((lane & 7) * 80 + ((lane >> 3) & 1) * 16);

    int bufidx = 0;
    for (int kt = 0; kt < T; ++kt) {
        if (kt < T - 1) { CP_WAIT(1); } else { CP_WAIT(0); }
        __syncthreads();

        if (kt + 2 < T) {
            int nbi = bufidx + 2; if (nbi >= 3) nbi -= 3;
            uint32_t nb_ = sb + nbi * BUF1_B;
            int k0 = (kt + 2) * 32;
            load_tile_async(nb_,          A + k0,  lda, tid);
            load_tile_async(nb_ + TILE_B, Bh + k0, lda, tid);
            CP_COMMIT();
        }

        uint32_t buf = sb + bufidx * BUF1_B;
        #pragma unroll
        for (int ks = 0; ks < 2; ++ks) {
            uint32_t ah[4][4], bh[4][2];
            uint32_t abase = buf + wm * (64 * 80) + a_lane_off + ks * 32;
            #pragma unroll
            for (int mi = 0; mi < 4; ++mi)
                ldm_x4(ah[mi], abase + mi * (16 * 80));
            uint32_t bbase = buf + TILE_B + wn * (32 * 80) + b_lane_off + ks * 32;
            #pragma unroll
            for (int ni = 0; ni < 4; ++ni)
                ldm_x2(bh[ni], bbase + ni * (8 * 80));
            #pragma unroll
            for (int mi = 0; mi < 4; ++mi)
                #pragma unroll
                for (int ni = 0; ni < 4; ++ni)
                    mma_f16(acc[mi][ni], ah[mi], bh[ni]);
        }
        if (++bufidx == 3) bufidx = 0;
    }

    #pragma unroll
    for (int mi = 0; mi < 4; ++mi) {
        int row = wm * 64 + mi * 16 + (lane >> 2);
        #pragma unroll
        for (int ni = 0; ni < 4; ++ni) {
            int col = wn * 32 + ni * 8 + (lane & 3) * 2;
            *(float2*)&C[(size_t)row * N + col] =
                make_float2(acc[mi][ni][0], acc[mi][ni][1]);
            *(float2*)&C[(size_t)(row + 8) * N + col] =
                make_float2(acc[mi][ni][2], acc[mi][ni][3]);
        }
    }
}

// fused QKV projection, split-K=2: z selects K-half and output buffer set
__global__ __launch_bounds__(256, 2)
void qkv_gemm_kernel(const __half* __restrict__ A,
                     const __half* __restrict__ Wq,
                     const __half* __restrict__ Wk,
                     const __half* __restrict__ Wv,
                     float* __restrict__ Cq0, float* __restrict__ Ck0,
                     float* __restrict__ Cv0,
                     float* __restrict__ Cq1, float* __restrict__ Ck1,
                     float* __restrict__ Cv1)
{
    extern __shared__ char smp[];
    uint32_t sb = smem_to_u32(smp);
    const int nb = blockIdx.x;
    const int bm = blockIdx.y * 128;
    const int z  = blockIdx.z;
    const int k0 = z * (HID_ / 2);
    const __half* Bh;
    float* C;
    int N, bn;
    if (nb < 16)      { Bh = Wq; C = z ? Cq1 : Cq0; N = HID_; bn = nb * 128; }
    else if (nb < 20) { Bh = Wk; C = z ? Ck1 : Ck0; N = KVD_; bn = (nb - 16) * 128; }
    else              { Bh = Wv; C = z ? Cv1 : Cv0; N = KVD_; bn = (nb - 20) * 128; }
    gemm1_body(sb,
               A + (size_t)bm * HID_ + k0, Bh + (size_t)bn * HID_ + k0,
               C + (size_t)bm * N + bn, N, HID_ / 2, HID_, threadIdx.x);
}

// Wo projection (1-product fp16, full K)
__global__ __launch_bounds__(256, 2)
void gemm1_mma_kernel(const __half* __restrict__ A,
                      const __half* __restrict__ Bh,
                      float* __restrict__ C, int N, int K)
{
    extern __shared__ char smp[];
    uint32_t sb = smem_to_u32(smp);
    const int bm = blockIdx.y * 128, bn = blockIdx.x * 128;
    gemm1_body(sb,
               A + (size_t)bm * K, Bh + (size_t)bn * K,
               C + (size_t)bm * N + bn, N, K, K, threadIdx.x);
}

// ---------------------------------------------------------------------------
// RoPE / layout kernels (sum the two split-K halves)
// ---------------------------------------------------------------------------
__global__ void rope_q_kernel(const int* __restrict__ positions,
                              __half* __restrict__ qh,
                              __half* __restrict__ ql)
{
    int idx = blockIdx.x * blockDim.x + threadIdx.x;
    int d = idx & 63;
    int s = (idx >> 6) & (S_ - 1);
    int h = idx >> 17;
    size_t base = (size_t)s * HID_ + h * HD_;
    float x1 = g_q[base + d]      + g_q2[base + d];
    float x2 = g_q[base + d + 64] + g_q2[base + d + 64];
    float o1, o2;
    rope_pair(x1, x2, positions[s], d, o1, o2);
    o1 *= SCL_LOG2E; o2 *= SCL_LOG2E;
    split_f16(o1, &qh[base + d],      &ql[base + d]);
    split_f16(o2, &qh[base + d + 64], &ql[base + d + 64]);
}

__global__ void rope_k_kernel(const int* __restrict__ positions,
                              float* __restrict__ kout,
                              __half* __restrict__ kb)
{
    int idx = blockIdx.x * blockDim.x + threadIdx.x;
    int d  = idx & 63;
    int s  = (idx >> 6) & (S_ - 1);
    int kv = idx >> 17;
    size_t src = (size_t)s * KVD_ + kv * HD_;
    float x1 = g_k[src + d]      + g_k2[src + d];
    float x2 = g_k[src + d + 64] + g_k2[src + d + 64];
    float o1, o2;
    rope_pair(x1, x2, positions[s], d, o1, o2);
    #pragma unroll
    for (int g = 0; g < GRP_; ++g) {
        size_t dst = ((size_t)(kv * GRP_ + g) * S_ + s) * HD_;
        kout[dst + d] = o1; kout[dst + d + 64] = o2;
    }
    size_t cb = ((size_t)kv * S_ + s) * HD_;
    kb[cb + d]      = __float2half_rn(o1);
    kb[cb + d + 64] = __float2half_rn(o2);
}

__global__ void copy_v_kernel(float* __restrict__ vout,
                              __half* __restrict__ vb)
{
    int idx = blockIdx.x * blockDim.x + threadIdx.x;
    int d4 = idx & 31;
    int s  = (idx >> 5) & (S_ - 1);
    int kv = idx >> 16;
    size_t so = (size_t)s * KVD_ + kv * HD_ + d4 * 4;
    float4 a = *(const float4*)&g_v[so];
    float4 b = *(const float4*)&g_v2[so];
    float4 v = make_float4(a.x + b.x, a.y + b.y, a.z + b.z, a.w + b.w);
    #pragma unroll
    for (int g = 0; g < GRP_; ++g)
        *(float4*)&vout[((size_t)(kv * GRP_ + g) * S_ + s) * HD_ + d4 * 4] = v;
    size_t cb = ((size_t)kv * S_ + s) * HD_ + d4 * 4;
    float f[4] = {v.x, v.y, v.z, v.w};
    union { uint2 u; __half b4[4]; } H;
    #pragma unroll
    for (int j = 0; j < 4; ++j) H.b4[j] = __float2half_rn(f[j]);
    *(uint2*)&vb[cb] = H.u;
}

// ---------------------------------------------------------------------------
// Tensor-core flash attention: BQ=64, BK=64, HD=128, 4 warps, 2 CTAs/SM.
// QK 2-product (Q hi/lo); PV single product. x4 ldmatrix pairing.
// ---------------------------------------------------------------------------
#define FSTR  272
#define FQ_B  (64*FSTR)
#define FKV_B (64*FSTR)
#define FLASH_SMEM (2*FQ_B + 4*FKV_B)   // 104448

__global__ __launch_bounds__(128, 2)
void flash_tc_kernel(const __half* __restrict__ qhp,
                     const __half* __restrict__ qlp,
                     const __half* __restrict__ khp,
                     const __half* __restrict__ vhp,
                     __half* __restrict__ at)
{
    extern __shared__ char smp[];
    const uint32_t sb = smem_to_u32(smp);
    const int tid = threadIdx.x, lane = tid & 31, w = tid >> 5;
    const int qb = 31 - blockIdx.x, h = blockIdx.y, kv = h >> 2;
    const int q0 = qb * 64;

    const uint32_t sQh = sb, sQl = sb + FQ_B;
    const uint32_t sKV = sb + 2 * FQ_B;

    {
        const __half* srch = qhp + (size_t)q0 * HID_ + h * HD_;
        const __half* srcl = qlp + (size_t)q0 * HID_ + h * HD_;
        #pragma unroll
        for (int c = tid; c < 1024; c += 128) {
            int r = c >> 4, seg = c & 15;
            cp16(sQh + r * FSTR + seg * 16, srch + (size_t)r * HID_ + seg * 8);
            cp16(sQl + r * FSTR + seg * 16, srcl + (size_t)r * HID_ + seg * 8);
        }
    }
    const __half* kb = khp + (size_t)kv * S_ * HD_;
    const __half* vb = vhp + (size_t)kv * S_ * HD_;

    auto load_kv = [&](int kt, uint32_t buf) {
        #pragma unroll
        for (int c = tid; c < 1024; c += 128) {
            int r = c >> 4, seg = c & 15;
            size_t g = (size_t)(kt * 64 + r) * HD_ + seg * 8;
            uint32_t so = r * FSTR + seg * 16;
            cp16(buf + so,         kb + g);
            cp16(buf + FKV_B + so, vb + g);
        }
    };
    load_kv(0, sKV);
    CP_COMMIT();

    float o[16][4];
    #pragma unroll
    for (int j = 0; j < 16; ++j)
        #pragma unroll
        for (int q = 0; q < 4; ++q) o[j][q] = 0.f;
    float m0 = -1e30f, m1 = -1e30f, l0 = 0.f, l1 = 0.f;

    const int last = qb;
    const uint32_t a_off   = (lane & 15) * FSTR + (lane >> 4) * 16;
    // x4 B (non-trans): m0/m1 = j fragment (k halves), m2/m3 = j+1
    const uint32_t bk4_off = (lane & 7) * FSTR + ((lane >> 3) & 1) * 16
                           + (lane >> 4) * (8 * FSTR);
    // x4 V (trans): m0/m1 = j fragment (row halves), m2/m3 = j+1 (next 8 cols)
    const uint32_t bv4_off = ((lane & 7) + ((lane >> 3) & 1) * 8) * FSTR
                           + (lane >> 4) * 16;
    const int r0 = q0 + w * 16 + (lane >> 2);

    for (int kt = 0; kt <= last; ++kt) {
        if (kt < last) {
            load_kv(kt + 1, sKV + ((kt + 1) & 1) * 2 * FKV_B);
            CP_COMMIT();
            CP_WAIT(1);
        } else {
            CP_WAIT(0);
        }
        __syncthreads();

        const uint32_t bK = sKV + (kt & 1) * 2 * FKV_B;
        const uint32_t bV = bK + FKV_B;

        float s[8][4];
        #pragma unroll
        for (int j = 0; j < 8; ++j)
            #pragma unroll
            for (int q = 0; q < 4; ++q) s[j][q] = 0.f;

        #pragma unroll
        for (int ks = 0; ks < 8; ++ks) {
            uint32_t ah[4], al[4], bh2[8][2];
            ldm_x4(ah, sQh + w * (16 * FSTR) + a_off + ks * 32);
            ldm_x4(al, sQl + w * (16 * FSTR) + a_off + ks * 32);
            #pragma unroll
            for (int j = 0; j < 8; j += 2) {
                uint32_t t4[4];
                ldm_x4(t4, bK + j * (8 * FSTR) + bk4_off + ks * 32);
                bh2[j][0] = t4[0];   bh2[j][1] = t4[1];
                bh2[j+1][0] = t4[2]; bh2[j+1][1] = t4[3];
            }
            #pragma unroll
            for (int j = 0; j < 8; ++j)
                mma_f16(s[j], ah, bh2[j]);
            #pragma unroll
            for (int j = 0; j < 8; ++j)
                mma_f16(s[j], al, bh2[j]);
        }

        if (kt == qb) {
            #pragma unroll
            for (int j = 0; j < 8; ++j) {
                int col = kt * 64 + j * 8 + (lane & 3) * 2;
                if (col     > r0)     s[j][0] = -3e4f;
                if (col + 1 > r0)     s[j][1] = -3e4f;
                if (col     > r0 + 8) s[j][2] = -3e4f;
                if (col + 1 > r0 + 8) s[j][3] = -3e4f;
            }
        }

        float mx0 = -3e4f, mx1 = -3e4f;
        #pragma unroll
        for (int j = 0; j < 8; ++j) {
            mx0 = fmaxf(mx0, fmaxf(s[j][0], s[j][1]));
            mx1 = fmaxf(mx1, fmaxf(s[j][2], s[j][3]));
        }
        mx0 = fmaxf(mx0, __shfl_xor_sync(0xffffffffu, mx0, 1));
        mx0 = fmaxf(mx0, __shfl_xor_sync(0xffffffffu, mx0, 2));
        mx1 = fmaxf(mx1, __shfl_xor_sync(0xffffffffu, mx1, 1));
        mx1 = fmaxf(mx1, __shfl_xor_sync(0xffffffffu, mx1, 2));

        const float mn0 = fmaxf(m0, mx0), mn1 = fmaxf(m1, mx1);
        const float al0 = fexp2(m0 - mn0), al1 = fexp2(m1 - mn1);
        m0 = mn0; m1 = mn1;

        float sum0 = 0.f, sum1 = 0.f;
        #pragma unroll
        for (int j = 0; j < 8; ++j) {
            s[j][0] = fexp2(s[j][0] - mn0);
            s[j][1] = fexp2(s[j][1] - mn0);
            s[j][2] = fexp2(s[j][2] - mn1);
            s[j][3] = fexp2(s[j][3] - mn1);
            sum0 += s[j][0] + s[j][1];
            sum1 += s[j][2] + s[j][3];
        }
        sum0 += __shfl_xor_sync(0xffffffffu, sum0, 1);
        sum0 += __shfl_xor_sync(0xffffffffu, sum0, 2);
        sum1 += __shfl_xor_sync(0xffffffffu, sum1, 1);
        sum1 += __shfl_xor_sync(0xffffffffu, sum1, 2);
        l0 = l0 * al0 + sum0;
        l1 = l1 * al1 + sum1;

        #pragma unroll
        for (int j = 0; j < 16; ++j) {
            o[j][0] *= al0; o[j][1] *= al0;
            o[j][2] *= al1; o[j][3] *= al1;
        }

        // ---- O += Ph Vh (x4 trans V loads, single product) ----
        #pragma unroll
        for (int pk = 0; pk < 4; ++pk) {
            uint32_t phi[4], vv[16][2];
            phi[0] = pack_hi(s[2*pk][0],   s[2*pk][1]);
            phi[1] = pack_hi(s[2*pk][2],   s[2*pk][3]);
            phi[2] = pack_hi(s[2*pk+1][0], s[2*pk+1][1]);
            phi[3] = pack_hi(s[2*pk+1][2], s[2*pk+1][3]);
            #pragma unroll
            for (int j = 0; j < 16; j += 2) {
                uint32_t t4[4];
                ldm_x4t(t4, bV + pk * (16 * FSTR) + bv4_off + j * 16);
                vv[j][0] = t4[0];   vv[j][1] = t4[1];
                vv[j+1][0] = t4[2]; vv[j+1][1] = t4[3];
            }
            #pragma unroll
            for (int j = 0; j < 16; ++j)
                mma_f16(o[j], phi, vv[j]);
        }
        __syncthreads();
    }

    const float inv0 = 1.f / l0, inv1 = 1.f / l1;
    #pragma unroll
    for (int j = 0; j < 16; ++j) {
        int col = j * 8 + (lane & 3) * 2;
        size_t off0 = (size_t)r0 * HID_ + h * HD_ + col;
        *(uint32_t*)&at[off0] = pack_hi(o[j][0] * inv0, o[j][1] * inv0);
        size_t off1 = (size_t)(r0 + 8) * HID_ + h * HD_ + col;
        *(uint32_t*)&at[off1] = pack_hi(o[j][2] * inv1, o[j][3] * inv1);
    }
}

// ---------------------------------------------------------------------------
extern "C" void kernel_launch(void* const* d_in, const int* in_sizes, int n_in,
                              void* d_out, int out_size)
{
    const float* hs  = (const float*)d_in[0];
    const int*   pos = (const int*)  d_in[1];
    const float* Wq  = (const float*)d_in[3];
    const float* Wk  = (const float*)d_in[4];
    const float* Wv  = (const float*)d_in[5];
    const float* Wo  = (const float*)d_in[6];

    float* out  = (float*)d_out;
    float* kout = out  + (size_t)S_ * HID_;
    float* vout = kout + (size_t)NH_ * S_ * HD_;

    float *qp, *kp, *vp, *qp2, *kp2, *vp2;
    cudaGetSymbolAddress((void**)&qp, g_q);   cudaGetSymbolAddress((void**)&qp2, g_q2);
    cudaGetSymbolAddress((void**)&kp, g_k);   cudaGetSymbolAddress((void**)&kp2, g_k2);
    cudaGetSymbolAddress((void**)&vp, g_v);   cudaGetSymbolAddress((void**)&vp2, g_v2);
    __half *hsp, *wq, *wk, *wv, *wo, *at;
    __half *qbh, *qbl, *kb, *vb;
    cudaGetSymbolAddress((void**)&hsp, g_hs);
    cudaGetSymbolAddress((void**)&wq, g_wq);
    cudaGetSymbolAddress((void**)&wk, g_wk);
    cudaGetSymbolAddress((void**)&wv, g_wv);
    cudaGetSymbolAddress((void**)&wo, g_wo);
    cudaGetSymbolAddress((void**)&at, g_at);
    cudaGetSymbolAddress((void**)&qbh, g_qb_hi); cudaGetSymbolAddress((void**)&qbl, g_qb_lo);
    cudaGetSymbolAddress((void**)&kb, g_kb);
    cudaGetSymbolAddress((void**)&vb, g_vb);

    cudaFuncSetAttribute(qkv_gemm_kernel,
                         cudaFuncAttributeMaxDynamicSharedMemorySize, GEMM1_SMEM);
    cudaFuncSetAttribute(gemm1_mma_kernel,
                         cudaFuncAttributeMaxDynamicSharedMemorySize, GEMM1_SMEM);
    cudaFuncSetAttribute(flash_tc_kernel,
                         cudaFuncAttributeMaxDynamicSharedMemorySize, FLASH_SMEM);

    conv_half_kernel<<<(S_*HID_/4)/256, 256>>>(hs, hsp);
    transpose_half2_kernel<<<dim3(HID_/32, HID_/32, 2), dim3(32,8)>>>(
        Wq, wq, Wo, wo, HID_, HID_);
    transpose_half2_kernel<<<dim3(KVD_/32, HID_/32, 2), dim3(32,8)>>>(
        Wk, wk, Wv, wv, HID_, KVD_);

    // fused QKV projection (1-product fp16, split-K=2)
    qkv_gemm_kernel<<<dim3(24, S_/128, 2), 256, GEMM1_SMEM>>>(
        hsp, wq, wk, wv, qp, kp, vp, qp2, kp2, vp2);

    rope_q_kernel<<<(NH_*S_*64)/256, 256>>>(pos, qbh, qbl);
    rope_k_kernel<<<(NKV_*S_*64)/256, 256>>>(pos, kout, kb);
    copy_v_kernel<<<(NKV_*S_*32)/256, 256>>>(vout, vb);

    flash_tc_kernel<<<dim3(32, NH_), 128, FLASH_SMEM>>>(
        qbh, qbl, kb, vb, at);

    gemm1_mma_kernel<<<dim3(HID_/128, S_/128), 256, GEMM1_SMEM>>>(
        at, wo, out, HID_, HID_);
}

// round 16
// speedup vs baseline: 1.1168x; 1.1168x over previous
#include <cuda_runtime.h>
#include <cuda_fp16.h>
#include <math.h>
#include <stdint.h>

#define S_   2048
#define HID_ 2048
#define NH_  16
#define NKV_ 4
#define GRP_ (NH_/NKV_)   // 4
#define HD_  128
#define KVD_ (NKV_*HD_)   // 512

#define SCL_LOG2E 0.12751744f

// ---------------------------------------------------------------------------
// scratch (allocation-free: __device__ globals)
// ---------------------------------------------------------------------------
__device__ float g_q [S_*HID_];
__device__ float g_k [S_*KVD_];
__device__ float g_v [S_*KVD_];

__device__ __half g_hs[S_*HID_];
__device__ __half g_wq[HID_*HID_];
__device__ __half g_wk[KVD_*HID_];
__device__ __half g_wv[KVD_*HID_];
__device__ __half g_wo[HID_*HID_];
__device__ __half g_at[S_*HID_];

__device__ __half g_qb[S_*HID_];          // roped Q*scl, single fp16
__device__ __half g_kb[NKV_*S_*HD_];
__device__ __half g_vb[NKV_*S_*HD_];

// ---------------------------------------------------------------------------
// PTX helpers (plain sm_103-safe)
// ---------------------------------------------------------------------------
__device__ __forceinline__ uint32_t smem_to_u32(const void* p) {
    uint32_t a;
    asm("{ .reg .u64 t; cvta.to.shared.u64 t, %1; cvt.u32.u64 %0, t; }"
        : "=r"(a) : "l"(p));
    return a;
}
__device__ __forceinline__ void cp16(uint32_t dst, const void* src) {
    asm volatile("cp.async.cg.shared.global [%0], [%1], 16;" :: "r"(dst), "l"(src));
}
#define CP_COMMIT() asm volatile("cp.async.commit_group;" ::: "memory")
#define CP_WAIT(n)  asm volatile("cp.async.wait_group %0;" :: "n"(n) : "memory")

__device__ __forceinline__ void ldm_x4(uint32_t* r, uint32_t addr) {
    asm volatile("ldmatrix.sync.aligned.m8n8.x4.shared.b16 {%0,%1,%2,%3}, [%4];"
        : "=r"(r[0]), "=r"(r[1]), "=r"(r[2]), "=r"(r[3]) : "r"(addr));
}
__device__ __forceinline__ void ldm_x4t(uint32_t* r, uint32_t addr) {
    asm volatile("ldmatrix.sync.aligned.m8n8.x4.trans.shared.b16 {%0,%1,%2,%3}, [%4];"
        : "=r"(r[0]), "=r"(r[1]), "=r"(r[2]), "=r"(r[3]) : "r"(addr));
}
__device__ __forceinline__ void mma_f16(float* c, const uint32_t* a, const uint32_t* b) {
    asm volatile("mma.sync.aligned.m16n8k16.row.col.f32.f16.f16.f32 "
        "{%0,%1,%2,%3}, {%4,%5,%6,%7}, {%8,%9}, {%0,%1,%2,%3};"
        : "+f"(c[0]), "+f"(c[1]), "+f"(c[2]), "+f"(c[3])
        : "r"(a[0]), "r"(a[1]), "r"(a[2]), "r"(a[3]), "r"(b[0]), "r"(b[1]));
}

__device__ __forceinline__ uint32_t pack_hi(float x, float y) {
    union { __half2 h2; uint32_t u; } H;
    H.h2 = __halves2half2(__float2half_rn(x), __float2half_rn(y));
    return H.u;
}

__device__ __forceinline__ float fexp2(float x) {
    x = fmaxf(x, -126.0f);
    int e = __float2int_rn(x);
    float f = x - (float)e;
    float p = 0.0018775767f;
    p = fmaf(p, f, 0.0089893397f);
    p = fmaf(p, f, 0.0558040221f);
    p = fmaf(p, f, 0.2402264923f);
    p = fmaf(p, f, 0.6931471825f);
    p = fmaf(p, f, 1.0f);
    return __int_as_float(__float_as_int(p) + (e << 23));
}

__device__ __forceinline__ void rope_pair(float x1, float x2, int pos, int d,
                                          float& o1, float& o2)
{
    float inv = exp2f((float)d * (-13.287712379549449f / 64.0f));
    float ang = (float)pos * inv;
    float sn, cs;
    sincosf(ang, &sn, &cs);
    o1 = x1 * cs - x2 * sn;
    o2 = x1 * sn + x2 * cs;
}

// ---------------------------------------------------------------------------
__global__ void conv_half_kernel(const float* __restrict__ src,
                                 __half* __restrict__ dst)
{
    int i = blockIdx.x * 256 + threadIdx.x;
    float4 v = ((const float4*)src)[i];
    union { uint2 u; __half b[4]; } H;
    H.b[0] = __float2half_rn(v.x); H.b[1] = __float2half_rn(v.y);
    H.b[2] = __float2half_rn(v.z); H.b[3] = __float2half_rn(v.w);
    ((uint2*)dst)[i] = H.u;
}

__global__ void transpose_half2_kernel(const float* __restrict__ W0,
                                       __half* __restrict__ O0,
                                       const float* __restrict__ W1,
                                       __half* __restrict__ O1,
                                       int Kd, int Nd)
{
    __shared__ float t[32][33];
    const float* W = blockIdx.z ? W1 : W0;
    __half* out    = blockIdx.z ? O1 : O0;
    int bn = blockIdx.x * 32;
    int bk = blockIdx.y * 32;
    int x = threadIdx.x, y = threadIdx.y;
    #pragma unroll
    for (int i = 0; i < 32; i += 8)
        t[y + i][x] = W[(size_t)(bk + y + i) * Nd + bn + x];
    __syncthreads();
    #pragma unroll
    for (int i = 0; i < 32; i += 8)
        out[(size_t)(bn + y + i) * Kd + bk + x] = __float2half_rn(t[x][y + i]);
}

// ---------------------------------------------------------------------------
// 1-product fp16 GEMM body: C = A @ Bh^T.  128x128 tile, K-chunks of 32,
// 3-stage cp.async, 2 CTAs/SM, paired x4 B loads.
// ---------------------------------------------------------------------------
#define TILE_B   10240
#define BUF1_B   (2*TILE_B)
#define GEMM1_SMEM (3*BUF1_B)   // 61440

__device__ __forceinline__ void load_tile_async(uint32_t sdst,
                                                const __half* g,
                                                int ldk, int tid)
{
    int r   = tid >> 2;
    int seg = tid & 3;
    #pragma unroll
    for (int h = 0; h < 2; ++h) {
        int row = r + h * 64;
        cp16(sdst + row * 80 + seg * 16, g + (size_t)row * ldk + seg * 8);
    }
}

__device__ __forceinline__ void gemm1_body(
    uint32_t sb,
    const __half* A, const __half* Bh,
    float* C, int N, int K, int tid)
{
    const int lane = tid & 31, wid = tid >> 5;
    const int wm = wid & 1, wn = wid >> 1;

    float acc[4][4][4];
    #pragma unroll
    for (int mi = 0; mi < 4; ++mi)
        #pragma unroll
        for (int ni = 0; ni < 4; ++ni)
            #pragma unroll
            for (int q = 0; q < 4; ++q) acc[mi][ni][q] = 0.f;

    const int T = K / 32;
    load_tile_async(sb,                   A,       K, tid);
    load_tile_async(sb + TILE_B,          Bh,      K, tid);
    CP_COMMIT();
    load_tile_async(sb + BUF1_B,          A + 32,  K, tid);
    load_tile_async(sb + BUF1_B + TILE_B, Bh + 32, K, tid);
    CP_COMMIT();

    const uint32_t a_lane_off  = (uint32_t)((lane & 15) * 80 + (lane >> 4) * 16);
    // paired x4 B: m0/m1 = frag ni (k halves), m2/m3 = frag ni+1
    const uint32_t b4_lane_off = (uint32_t)((lane & 7) * 80 + ((lane >> 3) & 1) * 16
                                            + (lane >> 4) * (8 * 80));

    int bufidx = 0;
    for (int kt = 0; kt < T; ++kt) {
        if (kt < T - 1) { CP_WAIT(1); } else { CP_WAIT(0); }
        __syncthreads();

        if (kt + 2 < T) {
            int nbi = bufidx + 2; if (nbi >= 3) nbi -= 3;
            uint32_t nb_ = sb + nbi * BUF1_B;
            int k0 = (kt + 2) * 32;
            load_tile_async(nb_,          A + k0,  K, tid);
            load_tile_async(nb_ + TILE_B, Bh + k0, K, tid);
            CP_COMMIT();
        }

        uint32_t buf = sb + bufidx * BUF1_B;
        #pragma unroll
        for (int ks = 0; ks < 2; ++ks) {
            uint32_t ah[4][4], bh[4][2];
            uint32_t abase = buf + wm * (64 * 80) + a_lane_off + ks * 32;
            #pragma unroll
            for (int mi = 0; mi < 4; ++mi)
                ldm_x4(ah[mi], abase + mi * (16 * 80));
            uint32_t bbase = buf + TILE_B + wn * (32 * 80) + b4_lane_off + ks * 32;
            #pragma unroll
            for (int ni = 0; ni < 4; ni += 2) {
                uint32_t t4[4];
                ldm_x4(t4, bbase + ni * (8 * 80));
                bh[ni][0] = t4[0];   bh[ni][1] = t4[1];
                bh[ni+1][0] = t4[2]; bh[ni+1][1] = t4[3];
            }
            #pragma unroll
            for (int mi = 0; mi < 4; ++mi)
                #pragma unroll
                for (int ni = 0; ni < 4; ++ni)
                    mma_f16(acc[mi][ni], ah[mi], bh[ni]);
        }
        if (++bufidx == 3) bufidx = 0;
    }

    #pragma unroll
    for (int mi = 0; mi < 4; ++mi) {
        int row = wm * 64 + mi * 16 + (lane >> 2);
        #pragma unroll
        for (int ni = 0; ni < 4; ++ni) {
            int col = wn * 32 + ni * 8 + (lane & 3) * 2;
            *(float2*)&C[(size_t)row * N + col] =
                make_float2(acc[mi][ni][0], acc[mi][ni][1]);
            *(float2*)&C[(size_t)(row + 8) * N + col] =
                make_float2(acc[mi][ni][2], acc[mi][ni][3]);
        }
    }
}

__global__ __launch_bounds__(256, 2)
void qkv_gemm_kernel(const __half* __restrict__ A,
                     const __half* __restrict__ Wq,
                     const __half* __restrict__ Wk,
                     const __half* __restrict__ Wv,
                     float* __restrict__ Cq, float* __restrict__ Ck,
                     float* __restrict__ Cv)
{
    extern __shared__ char smp[];
    uint32_t sb = smem_to_u32(smp);
    const int nb = blockIdx.x;
    const int bm = blockIdx.y * 128;
    const __half* Bh;
    float* C;
    int N, bn;
    if (nb < 16)      { Bh = Wq; C = Cq; N = HID_; bn = nb * 128; }
    else if (nb < 20) { Bh = Wk; C = Ck; N = KVD_; bn = (nb - 16) * 128; }
    else              { Bh = Wv; C = Cv; N = KVD_; bn = (nb - 20) * 128; }
    gemm1_body(sb,
               A + (size_t)bm * HID_, Bh + (size_t)bn * HID_,
               C + (size_t)bm * N + bn, N, HID_, threadIdx.x);
}

__global__ __launch_bounds__(256, 2)
void gemm1_mma_kernel(const __half* __restrict__ A,
                      const __half* __restrict__ Bh,
                      float* __restrict__ C, int N, int K)
{
    extern __shared__ char smp[];
    uint32_t sb = smem_to_u32(smp);
    const int bm = blockIdx.y * 128, bn = blockIdx.x * 128;
    gemm1_body(sb,
               A + (size_t)bm * K, Bh + (size_t)bn * K,
               C + (size_t)bm * N + bn, N, K, threadIdx.x);
}

// ---------------------------------------------------------------------------
// RoPE / layout kernels
// ---------------------------------------------------------------------------
__global__ void rope_q_kernel(const int* __restrict__ positions,
                              __half* __restrict__ qh)
{
    int idx = blockIdx.x * blockDim.x + threadIdx.x;
    int d = idx & 63;
    int s = (idx >> 6) & (S_ - 1);
    int h = idx >> 17;
    size_t base = (size_t)s * HID_ + h * HD_;
    float x1 = g_q[base + d], x2 = g_q[base + d + 64];
    float o1, o2;
    rope_pair(x1, x2, positions[s], d, o1, o2);
    qh[base + d]      = __float2half_rn(o1 * SCL_LOG2E);
    qh[base + d + 64] = __float2half_rn(o2 * SCL_LOG2E);
}

__global__ void rope_k_kernel(const int* __restrict__ positions,
                              float* __restrict__ kout,
                              __half* __restrict__ kb)
{
    int idx = blockIdx.x * blockDim.x + threadIdx.x;
    int d  = idx & 63;
    int s  = (idx >> 6) & (S_ - 1);
    int kv = idx >> 17;
    size_t src = (size_t)s * KVD_ + kv * HD_;
    float x1 = g_k[src + d], x2 = g_k[src + d + 64];
    float o1, o2;
    rope_pair(x1, x2, positions[s], d, o1, o2);
    #pragma unroll
    for (int g = 0; g < GRP_; ++g) {
        size_t dst = ((size_t)(kv * GRP_ + g) * S_ + s) * HD_;
        kout[dst + d] = o1; kout[dst + d + 64] = o2;
    }
    size_t cb = ((size_t)kv * S_ + s) * HD_;
    kb[cb + d]      = __float2half_rn(o1);
    kb[cb + d + 64] = __float2half_rn(o2);
}

__global__ void copy_v_kernel(float* __restrict__ vout,
                              __half* __restrict__ vb)
{
    int idx = blockIdx.x * blockDim.x + threadIdx.x;
    int d4 = idx & 31;
    int s  = (idx >> 5) & (S_ - 1);
    int kv = idx >> 16;
    float4 v = *(const float4*)&g_v[(size_t)s * KVD_ + kv * HD_ + d4 * 4];
    #pragma unroll
    for (int g = 0; g < GRP_; ++g)
        *(float4*)&vout[((size_t)(kv * GRP_ + g) * S_ + s) * HD_ + d4 * 4] = v;
    size_t cb = ((size_t)kv * S_ + s) * HD_ + d4 * 4;
    float f[4] = {v.x, v.y, v.z, v.w};
    union { uint2 u; __half b[4]; } H;
    #pragma unroll
    for (int j = 0; j < 4; ++j) H.b[j] = __float2half_rn(f[j]);
    *(uint2*)&vb[cb] = H.u;
}

// ---------------------------------------------------------------------------
// Tensor-core flash attention: BQ=64, BK=64, HD=128, 4 warps, 2 CTAs/SM.
// QK single product; PV single product. x4 ldmatrix pairing everywhere.
// ---------------------------------------------------------------------------
#define FSTR  272
#define FQ_B  (64*FSTR)
#define FKV_B (64*FSTR)
#define FLASH_SMEM (FQ_B + 4*FKV_B)   // 87040

__global__ __launch_bounds__(128, 2)
void flash_tc_kernel(const __half* __restrict__ qhp,
                     const __half* __restrict__ khp,
                     const __half* __restrict__ vhp,
                     __half* __restrict__ at)
{
    extern __shared__ char smp[];
    const uint32_t sb = smem_to_u32(smp);
    const int tid = threadIdx.x, lane = tid & 31, w = tid >> 5;
    const int qb = 31 - blockIdx.x, h = blockIdx.y, kv = h >> 2;
    const int q0 = qb * 64;

    const uint32_t sQh = sb;
    const uint32_t sKV = sb + FQ_B;

    {
        const __half* srch = qhp + (size_t)q0 * HID_ + h * HD_;
        #pragma unroll
        for (int c = tid; c < 1024; c += 128) {
            int r = c >> 4, seg = c & 15;
            cp16(sQh + r * FSTR + seg * 16, srch + (size_t)r * HID_ + seg * 8);
        }
    }
    const __half* kb = khp + (size_t)kv * S_ * HD_;
    const __half* vb = vhp + (size_t)kv * S_ * HD_;

    auto load_kv = [&](int kt, uint32_t buf) {
        #pragma unroll
        for (int c = tid; c < 1024; c += 128) {
            int r = c >> 4, seg = c & 15;
            size_t g = (size_t)(kt * 64 + r) * HD_ + seg * 8;
            uint32_t so = r * FSTR + seg * 16;
            cp16(buf + so,         kb + g);
            cp16(buf + FKV_B + so, vb + g);
        }
    };
    load_kv(0, sKV);
    CP_COMMIT();

    float o[16][4];
    #pragma unroll
    for (int j = 0; j < 16; ++j)
        #pragma unroll
        for (int q = 0; q < 4; ++q) o[j][q] = 0.f;
    float m0 = -1e30f, m1 = -1e30f, l0 = 0.f, l1 = 0.f;

    const int last = qb;
    const uint32_t a_off   = (lane & 15) * FSTR + (lane >> 4) * 16;
    const uint32_t bk4_off = (lane & 7) * FSTR + ((lane >> 3) & 1) * 16
                           + (lane >> 4) * (8 * FSTR);
    const uint32_t bv4_off = ((lane & 7) + ((lane >> 3) & 1) * 8) * FSTR
                           + (lane >> 4) * 16;
    const int r0 = q0 + w * 16 + (lane >> 2);

    for (int kt = 0; kt <= last; ++kt) {
        if (kt < last) {
            load_kv(kt + 1, sKV + ((kt + 1) & 1) * 2 * FKV_B);
            CP_COMMIT();
            CP_WAIT(1);
        } else {
            CP_WAIT(0);
        }
        __syncthreads();

        const uint32_t bK = sKV + (kt & 1) * 2 * FKV_B;
        const uint32_t bV = bK + FKV_B;

        float s[8][4];
        #pragma unroll
        for (int j = 0; j < 8; ++j)
            #pragma unroll
            for (int q = 0; q < 4; ++q) s[j][q] = 0.f;

        #pragma unroll
        for (int ks = 0; ks < 8; ++ks) {
            uint32_t ah[4], bh2[8][2];
            ldm_x4(ah, sQh + w * (16 * FSTR) + a_off + ks * 32);
            #pragma unroll
            for (int j = 0; j < 8; j += 2) {
                uint32_t t4[4];
                ldm_x4(t4, bK + j * (8 * FSTR) + bk4_off + ks * 32);
                bh2[j][0] = t4[0];   bh2[j][1] = t4[1];
                bh2[j+1][0] = t4[2]; bh2[j+1][1] = t4[3];
            }
            #pragma unroll
            for (int j = 0; j < 8; ++j)
                mma_f16(s[j], ah, bh2[j]);
        }

        if (kt == qb) {
            #pragma unroll
            for (int j = 0; j < 8; ++j) {
                int col = kt * 64 + j * 8 + (lane & 3) * 2;
                if (col     > r0)     s[j][0] = -3e4f;
                if (col + 1 > r0)     s[j][1] = -3e4f;
                if (col     > r0 + 8) s[j][2] = -3e4f;
                if (col + 1 > r0 + 8) s[j][3] = -3e4f;
            }
        }

        float mx0 = -3e4f, mx1 = -3e4f;
        #pragma unroll
        for (int j = 0; j < 8; ++j) {
            mx0 = fmaxf(mx0, fmaxf(s[j][0], s[j][1]));
            mx1 = fmaxf(mx1, fmaxf(s[j][2], s[j][3]));
        }
        mx0 = fmaxf(mx0, __shfl_xor_sync(0xffffffffu, mx0, 1));
        mx0 = fmaxf(mx0, __shfl_xor_sync(0xffffffffu, mx0, 2));
        mx1 = fmaxf(mx1, __shfl_xor_sync(0xffffffffu, mx1, 1));
        mx1 = fmaxf(mx1, __shfl_xor_sync(0xffffffffu, mx1, 2));

        const float mn0 = fmaxf(m0, mx0), mn1 = fmaxf(m1, mx1);
        const float al0 = fexp2(m0 - mn0), al1 = fexp2(m1 - mn1);
        m0 = mn0; m1 = mn1;

        float sum0 = 0.f, sum1 = 0.f;
        #pragma unroll
        for (int j = 0; j < 8; ++j) {
            s[j][0] = fexp2(s[j][0] - mn0);
            s[j][1] = fexp2(s[j][1] - mn0);
            s[j][2] = fexp2(s[j][2] - mn1);
            s[j][3] = fexp2(s[j][3] - mn1);
            sum0 += s[j][0] + s[j][1];
            sum1 += s[j][2] + s[j][3];
        }
        sum0 += __shfl_xor_sync(0xffffffffu, sum0, 1);
        sum0 += __shfl_xor_sync(0xffffffffu, sum0, 2);
        sum1 += __shfl_xor_sync(0xffffffffu, sum1, 1);
        sum1 += __shfl_xor_sync(0xffffffffu, sum1, 2);
        l0 = l0 * al0 + sum0;
        l1 = l1 * al1 + sum1;

        #pragma unroll
        for (int j = 0; j < 16; ++j) {
            o[j][0] *= al0; o[j][1] *= al0;
            o[j][2] *= al1; o[j][3] *= al1;
        }

        #pragma unroll
        for (int pk = 0; pk < 4; ++pk) {
            uint32_t phi[4], vv[16][2];
            phi[0] = pack_hi(s[2*pk][0],   s[2*pk][1]);
            phi[1] = pack_hi(s[2*pk][2],   s[2*pk][3]);
            phi[2] = pack_hi(s[2*pk+1][0], s[2*pk+1][1]);
            phi[3] = pack_hi(s[2*pk+1][2], s[2*pk+1][3]);
            #pragma unroll
            for (int j = 0; j < 16; j += 2) {
                uint32_t t4[4];
                ldm_x4t(t4, bV + pk * (16 * FSTR) + bv4_off + j * 16);
                vv[j][0] = t4[0];   vv[j][1] = t4[1];
                vv[j+1][0] = t4[2]; vv[j+1][1] = t4[3];
            }
            #pragma unroll
            for (int j = 0; j < 16; ++j)
                mma_f16(o[j], phi, vv[j]);
        }
        __syncthreads();
    }

    const float inv0 = 1.f / l0, inv1 = 1.f / l1;
    #pragma unroll
    for (int j = 0; j < 16; ++j) {
        int col = j * 8 + (lane & 3) * 2;
        size_t off0 = (size_t)r0 * HID_ + h * HD_ + col;
        *(uint32_t*)&at[off0] = pack_hi(o[j][0] * inv0, o[j][1] * inv0);
        size_t off1 = (size_t)(r0 + 8) * HID_ + h * HD_ + col;
        *(uint32_t*)&at[off1] = pack_hi(o[j][2] * inv1, o[j][3] * inv1);
    }
}

// ---------------------------------------------------------------------------
extern "C" void kernel_launch(void* const* d_in, const int* in_sizes, int n_in,
                              void* d_out, int out_size)
{
    const float* hs  = (const float*)d_in[0];
    const int*   pos = (const int*)  d_in[1];
    const float* Wq  = (const float*)d_in[3];
    const float* Wk  = (const float*)d_in[4];
    const float* Wv  = (const float*)d_in[5];
    const float* Wo  = (const float*)d_in[6];

    float* out  = (float*)d_out;
    float* kout = out  + (size_t)S_ * HID_;
    float* vout = kout + (size_t)NH_ * S_ * HD_;

    float *qp, *kp, *vp;
    cudaGetSymbolAddress((void**)&qp, g_q);
    cudaGetSymbolAddress((void**)&kp, g_k);
    cudaGetSymbolAddress((void**)&vp, g_v);
    __half *hsp, *wq, *wk, *wv, *wo, *at;
    __half *qbh, *kb, *vb;
    cudaGetSymbolAddress((void**)&hsp, g_hs);
    cudaGetSymbolAddress((void**)&wq, g_wq);
    cudaGetSymbolAddress((void**)&wk, g_wk);
    cudaGetSymbolAddress((void**)&wv, g_wv);
    cudaGetSymbolAddress((void**)&wo, g_wo);
    cudaGetSymbolAddress((void**)&at, g_at);
    cudaGetSymbolAddress((void**)&qbh, g_qb);
    cudaGetSymbolAddress((void**)&kb, g_kb);
    cudaGetSymbolAddress((void**)&vb, g_vb);

    cudaFuncSetAttribute(qkv_gemm_kernel,
                         cudaFuncAttributeMaxDynamicSharedMemorySize, GEMM1_SMEM);
    cudaFuncSetAttribute(gemm1_mma_kernel,
                         cudaFuncAttributeMaxDynamicSharedMemorySize, GEMM1_SMEM);
    cudaFuncSetAttribute(flash_tc_kernel,
                         cudaFuncAttributeMaxDynamicSharedMemorySize, FLASH_SMEM);

    conv_half_kernel<<<(S_*HID_/4)/256, 256>>>(hs, hsp);
    transpose_half2_kernel<<<dim3(HID_/32, HID_/32, 2), dim3(32,8)>>>(
        Wq, wq, Wo, wo, HID_, HID_);
    transpose_half2_kernel<<<dim3(KVD_/32, HID_/32, 2), dim3(32,8)>>>(
        Wk, wk, Wv, wv, HID_, KVD_);

    qkv_gemm_kernel<<<dim3(24, S_/128), 256, GEMM1_SMEM>>>(
        hsp, wq, wk, wv, qp, kp, vp);

    rope_q_kernel<<<(NH_*S_*64)/256, 256>>>(pos, qbh);
    rope_k_kernel<<<(NKV_*S_*64)/256, 256>>>(pos, kout, kb);
    copy_v_kernel<<<(NKV_*S_*32)/256, 256>>>(vout, vb);

    flash_tc_kernel<<<dim3(32, NH_), 128, FLASH_SMEM>>>(
        qbh, kb, vb, at);

    gemm1_mma_kernel<<<dim3(HID_/128, S_/128), 256, GEMM1_SMEM>>>(
        at, wo, out, HID_, HID_);
}

// round 17
// speedup vs baseline: 1.2047x; 1.0787x over previous
#include <cuda_runtime.h>
#include <cuda_fp16.h>
#include <math.h>
#include <stdint.h>

#define S_   2048
#define HID_ 2048
#define NH_  16
#define NKV_ 4
#define GRP_ (NH_/NKV_)   // 4
#define HD_  128
#define KVD_ (NKV_*HD_)   // 512

#define SCL_LOG2E 0.12751744f

// ---------------------------------------------------------------------------
// scratch (allocation-free: __device__ globals)
// ---------------------------------------------------------------------------
__device__ float g_q [S_*HID_];
__device__ float g_k [S_*KVD_];
__device__ float g_v [S_*KVD_];

__device__ __half g_hs[S_*HID_];
__device__ __half g_wq[HID_*HID_];
__device__ __half g_wk[KVD_*HID_];
__device__ __half g_wv[KVD_*HID_];
__device__ __half g_wo[HID_*HID_];
__device__ __half g_at[S_*HID_];

__device__ __half g_qb[S_*HID_];
__device__ __half g_kb[NKV_*S_*HD_];
__device__ __half g_vb[NKV_*S_*HD_];

// ---------------------------------------------------------------------------
// PTX helpers
// ---------------------------------------------------------------------------
__device__ __forceinline__ uint32_t smem_to_u32(const void* p) {
    uint32_t a;
    asm("{ .reg .u64 t; cvta.to.shared.u64 t, %1; cvt.u32.u64 %0, t; }"
        : "=r"(a) : "l"(p));
    return a;
}
__device__ __forceinline__ void cp16(uint32_t dst, const void* src) {
    asm volatile("cp.async.cg.shared.global [%0], [%1], 16;" :: "r"(dst), "l"(src));
}
#define CP_COMMIT() asm volatile("cp.async.commit_group;" ::: "memory")
#define CP_WAIT(n)  asm volatile("cp.async.wait_group %0;" :: "n"(n) : "memory")

__device__ __forceinline__ void ldm_x4(uint32_t* r, uint32_t addr) {
    asm volatile("ldmatrix.sync.aligned.m8n8.x4.shared.b16 {%0,%1,%2,%3}, [%4];"
        : "=r"(r[0]), "=r"(r[1]), "=r"(r[2]), "=r"(r[3]) : "r"(addr));
}
__device__ __forceinline__ void ldm_x4t(uint32_t* r, uint32_t addr) {
    asm volatile("ldmatrix.sync.aligned.m8n8.x4.trans.shared.b16 {%0,%1,%2,%3}, [%4];"
        : "=r"(r[0]), "=r"(r[1]), "=r"(r[2]), "=r"(r[3]) : "r"(addr));
}
__device__ __forceinline__ void mma_f16(float* c, const uint32_t* a, const uint32_t* b) {
    asm volatile("mma.sync.aligned.m16n8k16.row.col.f32.f16.f16.f32 "
        "{%0,%1,%2,%3}, {%4,%5,%6,%7}, {%8,%9}, {%0,%1,%2,%3};"
        : "+f"(c[0]), "+f"(c[1]), "+f"(c[2]), "+f"(c[3])
        : "r"(a[0]), "r"(a[1]), "r"(a[2]), "r"(a[3]), "r"(b[0]), "r"(b[1]));
}

__device__ __forceinline__ uint32_t pack_hi(float x, float y) {
    union { __half2 h2; uint32_t u; } H;
    H.h2 = __halves2half2(__float2half_rn(x), __float2half_rn(y));
    return H.u;
}

__device__ __forceinline__ float fexp2(float x) {
    x = fmaxf(x, -126.0f);
    int e = __float2int_rn(x);
    float f = x - (float)e;
    float p = 0.0018775767f;
    p = fmaf(p, f, 0.0089893397f);
    p = fmaf(p, f, 0.0558040221f);
    p = fmaf(p, f, 0.2402264923f);
    p = fmaf(p, f, 0.6931471825f);
    p = fmaf(p, f, 1.0f);
    return __int_as_float(__float_as_int(p) + (e << 23));
}

__device__ __forceinline__ void rope_pair(float x1, float x2, int pos, int d,
                                          float& o1, float& o2)
{
    float inv = exp2f((float)d * (-13.287712379549449f / 64.0f));
    float ang = (float)pos * inv;
    float sn, cs;
    sincosf(ang, &sn, &cs);
    o1 = x1 * cs - x2 * sn;
    o2 = x1 * sn + x2 * cs;
}

// ---------------------------------------------------------------------------
__global__ void conv_half_kernel(const float* __restrict__ src,
                                 __half* __restrict__ dst)
{
    int i = blockIdx.x * 256 + threadIdx.x;
    float4 v = ((const float4*)src)[i];
    union { uint2 u; __half b[4]; } H;
    H.b[0] = __float2half_rn(v.x); H.b[1] = __float2half_rn(v.y);
    H.b[2] = __float2half_rn(v.z); H.b[3] = __float2half_rn(v.w);
    ((uint2*)dst)[i] = H.u;
}

__global__ void transpose_half2_kernel(const float* __restrict__ W0,
                                       __half* __restrict__ O0,
                                       const float* __restrict__ W1,
                                       __half* __restrict__ O1,
                                       int Kd, int Nd)
{
    __shared__ float t[32][33];
    const float* W = blockIdx.z ? W1 : W0;
    __half* out    = blockIdx.z ? O1 : O0;
    int bn = blockIdx.x * 32;
    int bk = blockIdx.y * 32;
    int x = threadIdx.x, y = threadIdx.y;
    #pragma unroll
    for (int i = 0; i < 32; i += 8)
        t[y + i][x] = W[(size_t)(bk + y + i) * Nd + bn + x];
    __syncthreads();
    #pragma unroll
    for (int i = 0; i < 32; i += 8)
        out[(size_t)(bn + y + i) * Kd + bk + x] = __float2half_rn(t[x][y + i]);
}

// ---------------------------------------------------------------------------
// 1-product fp16 GEMM: C = A @ Bh^T. 128x128 tile, K-chunks of 64 (144B rows),
// 3-stage cp.async, 2 CTAs/SM, paired x4 B loads.
// ---------------------------------------------------------------------------
#define T64_B    18432              // 128 * 144
#define BUF64_B  (2*T64_B)          // 36864
#define GEMM1_SMEM (3*BUF64_B)      // 110592

__device__ __forceinline__ void load_tile64(uint32_t sdst,
                                            const __half* g,
                                            int ldk, int tid)
{
    #pragma unroll
    for (int q = 0; q < 4; ++q) {
        int slot = tid + q * 256;       // 1024 x 16B
        int r = slot >> 3, seg = slot & 7;
        cp16(sdst + r * 144 + seg * 16, g + (size_t)r * ldk + seg * 8);
    }
}

__device__ __forceinline__ void gemm1_body(
    uint32_t sb,
    const __half* A, const __half* Bh,
    float* C, int N, int K, int tid)
{
    const int lane = tid & 31, wid = tid >> 5;
    const int wm = wid & 1, wn = wid >> 1;

    float acc[4][4][4];
    #pragma unroll
    for (int mi = 0; mi < 4; ++mi)
        #pragma unroll
        for (int ni = 0; ni < 4; ++ni)
            #pragma unroll
            for (int q = 0; q < 4; ++q) acc[mi][ni][q] = 0.f;

    const int T = K / 64;
    load_tile64(sb,                  A,       K, tid);
    load_tile64(sb + T64_B,          Bh,      K, tid);
    CP_COMMIT();
    load_tile64(sb + BUF64_B,         A + 64,  K, tid);
    load_tile64(sb + BUF64_B + T64_B, Bh + 64, K, tid);
    CP_COMMIT();

    const uint32_t a_lane_off  = (uint32_t)((lane & 15) * 144 + (lane >> 4) * 16);
    const uint32_t b4_lane_off = (uint32_t)((lane & 7) * 144 + ((lane >> 3) & 1) * 16
                                            + (lane >> 4) * (8 * 144));

    int bufidx = 0;
    for (int kt = 0; kt < T; ++kt) {
        if (kt < T - 1) { CP_WAIT(1); } else { CP_WAIT(0); }
        __syncthreads();

        if (kt + 2 < T) {
            int nbi = bufidx + 2; if (nbi >= 3) nbi -= 3;
            uint32_t nb_ = sb + nbi * BUF64_B;
            int k0 = (kt + 2) * 64;
            load_tile64(nb_,         A + k0,  K, tid);
            load_tile64(nb_ + T64_B, Bh + k0, K, tid);
            CP_COMMIT();
        }

        uint32_t buf = sb + bufidx * BUF64_B;
        #pragma unroll
        for (int ks = 0; ks < 4; ++ks) {
            uint32_t ah[4][4], bh[4][2];
            uint32_t abase = buf + wm * (64 * 144) + a_lane_off + ks * 32;
            #pragma unroll
            for (int mi = 0; mi < 4; ++mi)
                ldm_x4(ah[mi], abase + mi * (16 * 144));
            uint32_t bbase = buf + T64_B + wn * (32 * 144) + b4_lane_off + ks * 32;
            #pragma unroll
            for (int ni = 0; ni < 4; ni += 2) {
                uint32_t t4[4];
                ldm_x4(t4, bbase + ni * (8 * 144));
                bh[ni][0] = t4[0];   bh[ni][1] = t4[1];
                bh[ni+1][0] = t4[2]; bh[ni+1][1] = t4[3];
            }
            #pragma unroll
            for (int mi = 0; mi < 4; ++mi)
                #pragma unroll
                for (int ni = 0; ni < 4; ++ni)
                    mma_f16(acc[mi][ni], ah[mi], bh[ni]);
        }
        if (++bufidx == 3) bufidx = 0;
    }

    #pragma unroll
    for (int mi = 0; mi < 4; ++mi) {
        int row = wm * 64 + mi * 16 + (lane >> 2);
        #pragma unroll
        for (int ni = 0; ni < 4; ++ni) {
            int col = wn * 32 + ni * 8 + (lane & 3) * 2;
            *(float2*)&C[(size_t)row * N + col] =
                make_float2(acc[mi][ni][0], acc[mi][ni][1]);
            *(float2*)&C[(size_t)(row + 8) * N + col] =
                make_float2(acc[mi][ni][2], acc[mi][ni][3]);
        }
    }
}

__global__ __launch_bounds__(256, 2)
void qkv_gemm_kernel(const __half* __restrict__ A,
                     const __half* __restrict__ Wq,
                     const __half* __restrict__ Wk,
                     const __half* __restrict__ Wv,
                     float* __restrict__ Cq, float* __restrict__ Ck,
                     float* __restrict__ Cv)
{
    extern __shared__ char smp[];
    uint32_t sb = smem_to_u32(smp);
    const int nb = blockIdx.x;
    const int bm = blockIdx.y * 128;
    const __half* Bh;
    float* C;
    int N, bn;
    if (nb < 16)      { Bh = Wq; C = Cq; N = HID_; bn = nb * 128; }
    else if (nb < 20) { Bh = Wk; C = Ck; N = KVD_; bn = (nb - 16) * 128; }
    else              { Bh = Wv; C = Cv; N = KVD_; bn = (nb - 20) * 128; }
    gemm1_body(sb,
               A + (size_t)bm * HID_, Bh + (size_t)bn * HID_,
               C + (size_t)bm * N + bn, N, HID_, threadIdx.x);
}

__global__ __launch_bounds__(256, 2)
void gemm1_mma_kernel(const __half* __restrict__ A,
                      const __half* __restrict__ Bh,
                      float* __restrict__ C, int N, int K)
{
    extern __shared__ char smp[];
    uint32_t sb = smem_to_u32(smp);
    const int bm = blockIdx.y * 128, bn = blockIdx.x * 128;
    gemm1_body(sb,
               A + (size_t)bm * K, Bh + (size_t)bn * K,
               C + (size_t)bm * N + bn, N, K, threadIdx.x);
}

// ---------------------------------------------------------------------------
// RoPE / layout kernels
// ---------------------------------------------------------------------------
__global__ void rope_q_kernel(const int* __restrict__ positions,
                              __half* __restrict__ qh)
{
    int idx = blockIdx.x * blockDim.x + threadIdx.x;
    int d = idx & 63;
    int s = (idx >> 6) & (S_ - 1);
    int h = idx >> 17;
    size_t base = (size_t)s * HID_ + h * HD_;
    float x1 = g_q[base + d], x2 = g_q[base + d + 64];
    float o1, o2;
    rope_pair(x1, x2, positions[s], d, o1, o2);
    qh[base + d]      = __float2half_rn(o1 * SCL_LOG2E);
    qh[base + d + 64] = __float2half_rn(o2 * SCL_LOG2E);
}

// fused K-rope + V-copy: idx covers NKV*S*64 (d-pairs)
__global__ void rope_kv_kernel(const int* __restrict__ positions,
                               float* __restrict__ kout,
                               __half* __restrict__ kb,
                               float* __restrict__ vout,
                               __half* __restrict__ vb)
{
    int idx = blockIdx.x * blockDim.x + threadIdx.x;
    int d  = idx & 63;
    int s  = (idx >> 6) & (S_ - 1);
    int kv = idx >> 17;
    size_t src = (size_t)s * KVD_ + kv * HD_;
    // K: rope
    {
        float x1 = g_k[src + d], x2 = g_k[src + d + 64];
        float o1, o2;
        rope_pair(x1, x2, positions[s], d, o1, o2);
        #pragma unroll
        for (int g = 0; g < GRP_; ++g) {
            size_t dst = ((size_t)(kv * GRP_ + g) * S_ + s) * HD_;
            kout[dst + d] = o1; kout[dst + d + 64] = o2;
        }
        size_t cb = ((size_t)kv * S_ + s) * HD_;
        kb[cb + d]      = __float2half_rn(o1);
        kb[cb + d + 64] = __float2half_rn(o2);
    }
    // V: copy (two elements: d and d+64)
    {
        float v0 = g_v[src + d], v1 = g_v[src + d + 64];
        #pragma unroll
        for (int g = 0; g < GRP_; ++g) {
            size_t dst = ((size_t)(kv * GRP_ + g) * S_ + s) * HD_;
            vout[dst + d]      = v0;
            vout[dst + d + 64] = v1;
        }
        size_t cb = ((size_t)kv * S_ + s) * HD_;
        vb[cb + d]      = __float2half_rn(v0);
        vb[cb + d + 64] = __float2half_rn(v1);
    }
}

// ---------------------------------------------------------------------------
// Tensor-core flash attention: BQ=64, BK=64, HD=128, 4 warps, 2 CTAs/SM.
// QK single product; PV single product. x4 ldmatrix pairing everywhere.
// ---------------------------------------------------------------------------
#define FSTR  272
#define FQ_B  (64*FSTR)
#define FKV_B (64*FSTR)
#define FLASH_SMEM (FQ_B + 4*FKV_B)   // 87040

__global__ __launch_bounds__(128, 2)
void flash_tc_kernel(const __half* __restrict__ qhp,
                     const __half* __restrict__ khp,
                     const __half* __restrict__ vhp,
                     __half* __restrict__ at)
{
    extern __shared__ char smp[];
    const uint32_t sb = smem_to_u32(smp);
    const int tid = threadIdx.x, lane = tid & 31, w = tid >> 5;
    const int qb = 31 - blockIdx.x, h = blockIdx.y, kv = h >> 2;
    const int q0 = qb * 64;

    const uint32_t sQh = sb;
    const uint32_t sKV = sb + FQ_B;

    {
        const __half* srch = qhp + (size_t)q0 * HID_ + h * HD_;
        #pragma unroll
        for (int c = tid; c < 1024; c += 128) {
            int r = c >> 4, seg = c & 15;
            cp16(sQh + r * FSTR + seg * 16, srch + (size_t)r * HID_ + seg * 8);
        }
    }
    const __half* kb = khp + (size_t)kv * S_ * HD_;
    const __half* vb = vhp + (size_t)kv * S_ * HD_;

    auto load_kv = [&](int kt, uint32_t buf) {
        #pragma unroll
        for (int c = tid; c < 1024; c += 128) {
            int r = c >> 4, seg = c & 15;
            size_t g = (size_t)(kt * 64 + r) * HD_ + seg * 8;
            uint32_t so = r * FSTR + seg * 16;
            cp16(buf + so,         kb + g);
            cp16(buf + FKV_B + so, vb + g);
        }
    };
    load_kv(0, sKV);
    CP_COMMIT();

    float o[16][4];
    #pragma unroll
    for (int j = 0; j < 16; ++j)
        #pragma unroll
        for (int q = 0; q < 4; ++q) o[j][q] = 0.f;
    float m0 = -1e30f, m1 = -1e30f, l0 = 0.f, l1 = 0.f;

    const int last = qb;
    const uint32_t a_off   = (lane & 15) * FSTR + (lane >> 4) * 16;
    const uint32_t bk4_off = (lane & 7) * FSTR + ((lane >> 3) & 1) * 16
                           + (lane >> 4) * (8 * FSTR);
    const uint32_t bv4_off = ((lane & 7) + ((lane >> 3) & 1) * 8) * FSTR
                           + (lane >> 4) * 16;
    const int r0 = q0 + w * 16 + (lane >> 2);

    for (int kt = 0; kt <= last; ++kt) {
        if (kt < last) {
            load_kv(kt + 1, sKV + ((kt + 1) & 1) * 2 * FKV_B);
            CP_COMMIT();
            CP_WAIT(1);
        } else {
            CP_WAIT(0);
        }
        __syncthreads();

        const uint32_t bK = sKV + (kt & 1) * 2 * FKV_B;
        const uint32_t bV = bK + FKV_B;

        float s[8][4];
        #pragma unroll
        for (int j = 0; j < 8; ++j)
            #pragma unroll
            for (int q = 0; q < 4; ++q) s[j][q] = 0.f;

        #pragma unroll
        for (int ks = 0; ks < 8; ++ks) {
            uint32_t ah[4], bh2[8][2];
            ldm_x4(ah, sQh + w * (16 * FSTR) + a_off + ks * 32);
            #pragma unroll
            for (int j = 0; j < 8; j += 2) {
                uint32_t t4[4];
                ldm_x4(t4, bK + j * (8 * FSTR) + bk4_off + ks * 32);
                bh2[j][0] = t4[0];   bh2[j][1] = t4[1];
                bh2[j+1][0] = t4[2]; bh2[j+1][1] = t4[3];
            }
            #pragma unroll
            for (int j = 0; j < 8; ++j)
                mma_f16(s[j], ah, bh2[j]);
        }

        if (kt == qb) {
            #pragma unroll
            for (int j = 0; j < 8; ++j) {
                int col = kt * 64 + j * 8 + (lane & 3) * 2;
                if (col     > r0)     s[j][0] = -3e4f;
                if (col + 1 > r0)     s[j][1] = -3e4f;
                if (col     > r0 + 8) s[j][2] = -3e4f;
                if (col + 1 > r0 + 8) s[j][3] = -3e4f;
            }
        }

        float mx0 = -3e4f, mx1 = -3e4f;
        #pragma unroll
        for (int j = 0; j < 8; ++j) {
            mx0 = fmaxf(mx0, fmaxf(s[j][0], s[j][1]));
            mx1 = fmaxf(mx1, fmaxf(s[j][2], s[j][3]));
        }
        mx0 = fmaxf(mx0, __shfl_xor_sync(0xffffffffu, mx0, 1));
        mx0 = fmaxf(mx0, __shfl_xor_sync(0xffffffffu, mx0, 2));
        mx1 = fmaxf(mx1, __shfl_xor_sync(0xffffffffu, mx1, 1));
        mx1 = fmaxf(mx1, __shfl_xor_sync(0xffffffffu, mx1, 2));

        const float mn0 = fmaxf(m0, mx0), mn1 = fmaxf(m1, mx1);
        const float al0 = fexp2(m0 - mn0), al1 = fexp2(m1 - mn1);
        m0 = mn0; m1 = mn1;

        float sum0 = 0.f, sum1 = 0.f;
        #pragma unroll
        for (int j = 0; j < 8; ++j) {
            s[j][0] = fexp2(s[j][0] - mn0);
            s[j][1] = fexp2(s[j][1] - mn0);
            s[j][2] = fexp2(s[j][2] - mn1);
            s[j][3] = fexp2(s[j][3] - mn1);
            sum0 += s[j][0] + s[j][1];
            sum1 += s[j][2] + s[j][3];
        }
        sum0 += __shfl_xor_sync(0xffffffffu, sum0, 1);
        sum0 += __shfl_xor_sync(0xffffffffu, sum0, 2);
        sum1 += __shfl_xor_sync(0xffffffffu, sum1, 1);
        sum1 += __shfl_xor_sync(0xffffffffu, sum1, 2);
        l0 = l0 * al0 + sum0;
        l1 = l1 * al1 + sum1;

        #pragma unroll
        for (int j = 0; j < 16; ++j) {
            o[j][0] *= al0; o[j][1] *= al0;
            o[j][2] *= al1; o[j][3] *= al1;
        }

        #pragma unroll
        for (int pk = 0; pk < 4; ++pk) {
            uint32_t phi[4], vv[16][2];
            phi[0] = pack_hi(s[2*pk][0],   s[2*pk][1]);
            phi[1] = pack_hi(s[2*pk][2],   s[2*pk][3]);
            phi[2] = pack_hi(s[2*pk+1][0], s[2*pk+1][1]);
            phi[3] = pack_hi(s[2*pk+1][2], s[2*pk+1][3]);
            #pragma unroll
            for (int j = 0; j < 16; j += 2) {
                uint32_t t4[4];
                ldm_x4t(t4, bV + pk * (16 * FSTR) + bv4_off + j * 16);
                vv[j][0] = t4[0];   vv[j][1] = t4[1];
                vv[j+1][0] = t4[2]; vv[j+1][1] = t4[3];
            }
            #pragma unroll
            for (int j = 0; j < 16; ++j)
                mma_f16(o[j], phi, vv[j]);
        }
        __syncthreads();
    }

    const float inv0 = 1.f / l0, inv1 = 1.f / l1;
    #pragma unroll
    for (int j = 0; j < 16; ++j) {
        int col = j * 8 + (lane & 3) * 2;
        size_t off0 = (size_t)r0 * HID_ + h * HD_ + col;
        *(uint32_t*)&at[off0] = pack_hi(o[j][0] * inv0, o[j][1] * inv0);
        size_t off1 = (size_t)(r0 + 8) * HID_ + h * HD_ + col;
        *(uint32_t*)&at[off1] = pack_hi(o[j][2] * inv1, o[j][3] * inv1);
    }
}

// ---------------------------------------------------------------------------
extern "C" void kernel_launch(void* const* d_in, const int* in_sizes, int n_in,
                              void* d_out, int out_size)
{
    const float* hs  = (const float*)d_in[0];
    const int*   pos = (const int*)  d_in[1];
    const float* Wq  = (const float*)d_in[3];
    const float* Wk  = (const float*)d_in[4];
    const float* Wv  = (const float*)d_in[5];
    const float* Wo  = (const float*)d_in[6];

    float* out  = (float*)d_out;
    float* kout = out  + (size_t)S_ * HID_;
    float* vout = kout + (size_t)NH_ * S_ * HD_;

    float *qp, *kp, *vp;
    cudaGetSymbolAddress((void**)&qp, g_q);
    cudaGetSymbolAddress((void**)&kp, g_k);
    cudaGetSymbolAddress((void**)&vp, g_v);
    __half *hsp, *wq, *wk, *wv, *wo, *at;
    __half *qbh, *kb, *vb;
    cudaGetSymbolAddress((void**)&hsp, g_hs);
    cudaGetSymbolAddress((void**)&wq, g_wq);
    cudaGetSymbolAddress((void**)&wk, g_wk);
    cudaGetSymbolAddress((void**)&wv, g_wv);
    cudaGetSymbolAddress((void**)&wo, g_wo);
    cudaGetSymbolAddress((void**)&at, g_at);
    cudaGetSymbolAddress((void**)&qbh, g_qb);
    cudaGetSymbolAddress((void**)&kb, g_kb);
    cudaGetSymbolAddress((void**)&vb, g_vb);

    cudaFuncSetAttribute(qkv_gemm_kernel,
                         cudaFuncAttributeMaxDynamicSharedMemorySize, GEMM1_SMEM);
    cudaFuncSetAttribute(gemm1_mma_kernel,
                         cudaFuncAttributeMaxDynamicSharedMemorySize, GEMM1_SMEM);
    cudaFuncSetAttribute(flash_tc_kernel,
                         cudaFuncAttributeMaxDynamicSharedMemorySize, FLASH_SMEM);

    conv_half_kernel<<<(S_*HID_/4)/256, 256>>>(hs, hsp);
    transpose_half2_kernel<<<dim3(HID_/32, HID_/32, 2), dim3(32,8)>>>(
        Wq, wq, Wo, wo, HID_, HID_);
    transpose_half2_kernel<<<dim3(KVD_/32, HID_/32, 2), dim3(32,8)>>>(
        Wk, wk, Wv, wv, HID_, KVD_);

    qkv_gemm_kernel<<<dim3(24, S_/128), 256, GEMM1_SMEM>>>(
        hsp, wq, wk, wv, qp, kp, vp);

    rope_q_kernel<<<(NH_*S_*64)/256, 256>>>(pos, qbh);
    rope_kv_kernel<<<(NKV_*S_*64)/256, 256>>>(pos, kout, kb, vout, vb);

    flash_tc_kernel<<<dim3(32, NH_), 128, FLASH_SMEM>>>(
        qbh, kb, vb, at);

    gemm1_mma_kernel<<<dim3(HID_/128, S_/128), 256, GEMM1_SMEM>>>(
        at, wo, out, HID_, HID_);
}